// round 1
// baseline (speedup 1.0000x reference)
#include <cuda_runtime.h>
#include <cstdint>
#include <cstddef>

// Problem dims
#define LNUM 4
#define BB 2
#define SSEQ 1024
#define DDIM 1024
#define HH 16
#define DKK 64
#define FFD 4096
#define MM (BB * SSEQ)   // 2048 rows

// ---------------------------------------------------------------------------
// Scratch buffers (device globals — no allocations allowed)
// ---------------------------------------------------------------------------
__device__ float g_q[MM * DDIM];
__device__ float g_k[MM * DDIM];
__device__ float g_v[MM * DDIM];
__device__ float g_a[MM * DDIM];
__device__ float g_x1[MM * DDIM];
__device__ float g_y[MM * DDIM];
__device__ float g_tmp[MM * DDIM];
__device__ float g_h[MM * DDIM];
__device__ float g_hid[MM * FFD];

// ---------------------------------------------------------------------------
// SGEMM: C[M,N] = A[M,K] @ B + bias (+ residual) (+ relu)
// HEADED: B element at ((n>>6)*K + k)*64 + (n&63)   (weights laid out (H,D,DK))
// else:   B row-major [K,N]
// Tile: 128x128x8, 256 threads, 8x8 per thread.
// M,N multiples of 128; K multiple of 8. (Holds for all our shapes.)
// ---------------------------------------------------------------------------
template <bool HEADED, bool RELU, bool RESID>
__global__ __launch_bounds__(256)
void sgemm_kernel(const float* __restrict__ A, const float* __restrict__ B,
                  const float* __restrict__ bias, const float* __restrict__ R,
                  float* __restrict__ C, int M, int N, int K)
{
    __shared__ float As[8][128];
    __shared__ float Bs[8][128];

    const int tid = threadIdx.x;
    const int tr = tid >> 4;          // 0..15
    const int tc = tid & 15;          // 0..15
    const int row_blk = blockIdx.y * 128;
    const int col_blk = blockIdx.x * 128;

    // A tile loader: each thread one float4 (128x8 = 1024 floats / 256 thr)
    const int a_r = tid >> 1;         // 0..127
    const int a_c = (tid & 1) * 4;    // 0 or 4
    // B tile loader: each thread one float4 (8x128)
    const int b_k = tid >> 5;         // 0..7
    const int b_c = (tid & 31) * 4;   // 0..124

    float acc[8][8];
#pragma unroll
    for (int i = 0; i < 8; i++)
#pragma unroll
        for (int j = 0; j < 8; j++) acc[i][j] = 0.f;

    for (int k0 = 0; k0 < K; k0 += 8) {
        // load A tile (transposed into As[k][m])
        float4 av = *(const float4*)&A[(size_t)(row_blk + a_r) * K + k0 + a_c];
        As[a_c + 0][a_r] = av.x;
        As[a_c + 1][a_r] = av.y;
        As[a_c + 2][a_r] = av.z;
        As[a_c + 3][a_r] = av.w;
        // load B tile
        float4 bv;
        if (HEADED) {
            int n = col_blk + b_c;
            bv = *(const float4*)&B[((size_t)(n >> 6) * K + (k0 + b_k)) * 64 + (n & 63)];
        } else {
            bv = *(const float4*)&B[(size_t)(k0 + b_k) * N + col_blk + b_c];
        }
        *(float4*)&Bs[b_k][b_c] = bv;
        __syncthreads();

#pragma unroll
        for (int kk = 0; kk < 8; kk++) {
            float af[8], bf[8];
            *(float4*)&af[0] = *(const float4*)&As[kk][tr * 8];
            *(float4*)&af[4] = *(const float4*)&As[kk][tr * 8 + 4];
            *(float4*)&bf[0] = *(const float4*)&Bs[kk][tc * 8];
            *(float4*)&bf[4] = *(const float4*)&Bs[kk][tc * 8 + 4];
#pragma unroll
            for (int i = 0; i < 8; i++)
#pragma unroll
                for (int j = 0; j < 8; j++)
                    acc[i][j] += af[i] * bf[j];
        }
        __syncthreads();
    }

    const int row0 = row_blk + tr * 8;
    const int col0 = col_blk + tc * 8;
#pragma unroll
    for (int i = 0; i < 8; i++) {
#pragma unroll
        for (int j = 0; j < 8; j++) {
            float val = acc[i][j] + bias[col0 + j];
            if (RESID) val += R[(size_t)(row0 + i) * N + col0 + j];
            if (RELU)  val = fmaxf(val, 0.f);
            C[(size_t)(row0 + i) * N + col0 + j] = val;
        }
    }
}

// ---------------------------------------------------------------------------
// Flash attention: q,k,v in (B, S, H*DK) concat layout; out in same layout.
// One CTA per (b, h, 64-row q tile). Online softmax over kv tiles of 64.
// kv length = *maskp (attn1) or S (maskp == nullptr).
// ---------------------------------------------------------------------------
#define AP 65   // pitch for transposed 64x64 tiles
#define VP 68   // pitch for row-major V tile (float4-aligned)
#define ATTN_SMEM_FLOATS (3 * 64 * AP + 64 * VP + 3 * 64)
#define ATTN_SMEM_BYTES (ATTN_SMEM_FLOATS * 4)

__global__ __launch_bounds__(256)
void attn_kernel(const float* __restrict__ q, const float* __restrict__ k,
                 const float* __restrict__ v, float* __restrict__ out,
                 const int* __restrict__ maskp)
{
    extern __shared__ float sm[];
    float* Qs  = sm;                  // [64][AP] transposed: Qs[d*AP + r]
    float* Ks  = Qs + 64 * AP;        // [64][AP] transposed: Ks[d*AP + c]
    float* Ps  = Ks + 64 * AP;        // [64][AP] row-major scores/probs
    float* Vs  = Ps + 64 * AP;        // [64][VP] row-major: Vs[c*VP + d]
    float* mrow = Vs + 64 * VP;       // [64]
    float* lrow = mrow + 64;          // [64]
    float* srow = lrow + 64;          // [64]

    const int tid = threadIdx.x;
    const int tx = tid & 15;          // col group
    const int ty = tid >> 4;          // row group
    const int qt = blockIdx.x;
    const int h  = blockIdx.y;
    const int b  = blockIdx.z;

    int kvlen = maskp ? *maskp : SSEQ;
    if (kvlen > SSEQ) kvlen = SSEQ;
    if (kvlen < 1) kvlen = 1;

    const float* qb = q + ((size_t)(b * SSEQ) + qt * 64) * DDIM + h * DKK;
    const float* kb = k + (size_t)(b * SSEQ) * DDIM + h * DKK;
    const float* vb = v + (size_t)(b * SSEQ) * DDIM + h * DKK;

    // load Q tile (transposed)
#pragma unroll
    for (int c = 0; c < 4; c++) {
        int idx = tid + c * 256;
        int r = idx >> 4;
        int d0 = (idx & 15) * 4;
        float4 t = *(const float4*)&qb[(size_t)r * DDIM + d0];
        Qs[(d0 + 0) * AP + r] = t.x;
        Qs[(d0 + 1) * AP + r] = t.y;
        Qs[(d0 + 2) * AP + r] = t.z;
        Qs[(d0 + 3) * AP + r] = t.w;
    }
    if (tid < 64) { mrow[tid] = -1e30f; lrow[tid] = 0.f; }

    float O[4][4];
#pragma unroll
    for (int i = 0; i < 4; i++)
#pragma unroll
        for (int j = 0; j < 4; j++) O[i][j] = 0.f;

    const int nt = (kvlen + 63) >> 6;
    for (int t = 0; t < nt; t++) {
        __syncthreads();   // previous-iteration consumers of Ks/Vs done; Q/m/l init published
        const float* kt = kb + (size_t)(t * 64) * DDIM;
        const float* vt = vb + (size_t)(t * 64) * DDIM;
#pragma unroll
        for (int c = 0; c < 4; c++) {
            int idx = tid + c * 256;
            int r = idx >> 4;
            int d0 = (idx & 15) * 4;
            float4 tk = *(const float4*)&kt[(size_t)r * DDIM + d0];
            Ks[(d0 + 0) * AP + r] = tk.x;
            Ks[(d0 + 1) * AP + r] = tk.y;
            Ks[(d0 + 2) * AP + r] = tk.z;
            Ks[(d0 + 3) * AP + r] = tk.w;
            float4 tv = *(const float4*)&vt[(size_t)r * DDIM + d0];
            *(float4*)&Vs[r * VP + d0] = tv;
        }
        __syncthreads();

        // scores: s = (Q K^T) * 1/sqrt(64)
        float sacc[4][4];
#pragma unroll
        for (int i = 0; i < 4; i++)
#pragma unroll
            for (int j = 0; j < 4; j++) sacc[i][j] = 0.f;
#pragma unroll 8
        for (int d = 0; d < 64; d++) {
            float aq[4], bk[4];
#pragma unroll
            for (int i = 0; i < 4; i++) aq[i] = Qs[d * AP + ty * 4 + i];
#pragma unroll
            for (int j = 0; j < 4; j++) bk[j] = Ks[d * AP + tx * 4 + j];
#pragma unroll
            for (int i = 0; i < 4; i++)
#pragma unroll
                for (int j = 0; j < 4; j++) sacc[i][j] += aq[i] * bk[j];
        }
        const int cbase = t * 64 + tx * 4;
#pragma unroll
        for (int i = 0; i < 4; i++)
#pragma unroll
            for (int j = 0; j < 4; j++) {
                float val = (cbase + j < kvlen) ? sacc[i][j] * 0.125f : -1e30f;
                Ps[(ty * 4 + i) * AP + tx * 4 + j] = val;
            }
        __syncthreads();

        // per-row online softmax (one thread per row)
        if (tid < 64) {
            float mo = mrow[tid];
            float mt = -1e30f;
            float* pr = &Ps[tid * AP];
#pragma unroll 8
            for (int c = 0; c < 64; c++) mt = fmaxf(mt, pr[c]);
            float mn = fmaxf(mo, mt);
            float sc = __expf(mo - mn);
            float sum = 0.f;
#pragma unroll 8
            for (int c = 0; c < 64; c++) {
                float p = __expf(pr[c] - mn);
                pr[c] = p;
                sum += p;
            }
            lrow[tid] = lrow[tid] * sc + sum;
            mrow[tid] = mn;
            srow[tid] = sc;
        }
        __syncthreads();

        // rescale O, accumulate O += P @ V
        float sci[4];
#pragma unroll
        for (int i = 0; i < 4; i++) sci[i] = srow[ty * 4 + i];
#pragma unroll
        for (int i = 0; i < 4; i++)
#pragma unroll
            for (int j = 0; j < 4; j++) O[i][j] *= sci[i];
#pragma unroll 8
        for (int c = 0; c < 64; c++) {
            float pv[4];
#pragma unroll
            for (int i = 0; i < 4; i++) pv[i] = Ps[(ty * 4 + i) * AP + c];
            float4 vv = *(const float4*)&Vs[c * VP + tx * 4];
#pragma unroll
            for (int i = 0; i < 4; i++) {
                O[i][0] += pv[i] * vv.x;
                O[i][1] += pv[i] * vv.y;
                O[i][2] += pv[i] * vv.z;
                O[i][3] += pv[i] * vv.w;
            }
        }
    }
    __syncthreads();

    float* ob = out + ((size_t)(b * SSEQ) + qt * 64) * DDIM + h * DKK;
#pragma unroll
    for (int i = 0; i < 4; i++) {
        float inv = 1.f / lrow[ty * 4 + i];
#pragma unroll
        for (int j = 0; j < 4; j++)
            ob[(size_t)(ty * 4 + i) * DDIM + tx * 4 + j] = O[i][j] * inv;
    }
}

// ---------------------------------------------------------------------------
// BatchNorm over axes (B, D) per s index (channel axis = 1, S==D==1024).
// out[b,s,d] = g[s] * (x - mean_s) * rsqrt(var_s + eps) + be[s]
// One CTA per s. In-place safe (stats first, then writes).
// ---------------------------------------------------------------------------
__global__ __launch_bounds__(256)
void bn_kernel(const float* __restrict__ in, const float* __restrict__ g,
               const float* __restrict__ be, float* __restrict__ out)
{
    __shared__ float s_sum[256];
    __shared__ float s_sq[256];
    __shared__ float s_mean, s_rs;

    const int s = blockIdx.x;
    const int tid = threadIdx.x;

    float sum = 0.f, sq = 0.f;
#pragma unroll
    for (int b = 0; b < BB; b++) {
        const float* row = in + ((size_t)b * SSEQ + s) * DDIM;
        for (int d = tid; d < DDIM; d += 256) {
            float x = row[d];
            sum += x;
            sq += x * x;
        }
    }
    s_sum[tid] = sum;
    s_sq[tid] = sq;
    __syncthreads();
    for (int o = 128; o > 0; o >>= 1) {
        if (tid < o) { s_sum[tid] += s_sum[tid + o]; s_sq[tid] += s_sq[tid + o]; }
        __syncthreads();
    }
    if (tid == 0) {
        const float inv_n = 1.f / (BB * DDIM);
        float mean = s_sum[0] * inv_n;
        float var = s_sq[0] * inv_n - mean * mean;
        s_mean = mean;
        s_rs = rsqrtf(var + 1e-5f);
    }
    __syncthreads();
    const float gg = g[s], bb2 = be[s], mean = s_mean, rs = s_rs;
#pragma unroll
    for (int b = 0; b < BB; b++) {
        const float* row = in + ((size_t)b * SSEQ + s) * DDIM;
        float* orow = out + ((size_t)b * SSEQ + s) * DDIM;
        for (int d = tid; d < DDIM; d += 256) {
            orow[d] = (row[d] - mean) * rs * gg + bb2;
        }
    }
}

// ---------------------------------------------------------------------------
// Host orchestration
// ---------------------------------------------------------------------------
extern "C" void kernel_launch(void* const* d_in, const int* in_sizes, int n_in,
                              void* d_out, int out_size)
{
    const float* x   = (const float*)d_in[0];
    const float* Wq1 = (const float*)d_in[1];
    const float* bq1 = (const float*)d_in[2];
    const float* Wk1 = (const float*)d_in[3];
    const float* bk1 = (const float*)d_in[4];
    const float* Wv1 = (const float*)d_in[5];
    const float* bv1 = (const float*)d_in[6];
    const float* Wo1 = (const float*)d_in[7];
    const float* bo1 = (const float*)d_in[8];
    const float* Wq2 = (const float*)d_in[9];
    const float* bq2 = (const float*)d_in[10];
    const float* Wk2 = (const float*)d_in[11];
    const float* bk2 = (const float*)d_in[12];
    const float* Wv2 = (const float*)d_in[13];
    const float* bv2 = (const float*)d_in[14];
    const float* Wo2 = (const float*)d_in[15];
    const float* bo2 = (const float*)d_in[16];
    const float* g1  = (const float*)d_in[17];
    const float* be1 = (const float*)d_in[18];
    const float* g2  = (const float*)d_in[19];
    const float* be2 = (const float*)d_in[20];
    const float* g3  = (const float*)d_in[21];
    const float* be3 = (const float*)d_in[22];
    const float* W1  = (const float*)d_in[23];
    const float* bf1 = (const float*)d_in[24];
    const float* W2  = (const float*)d_in[25];
    const float* bf2 = (const float*)d_in[26];
    const int*   maskp = (const int*)d_in[27];

    float *q, *k, *v, *a, *x1, *y, *tmp, *h, *hid;
    cudaGetSymbolAddress((void**)&q,   g_q);
    cudaGetSymbolAddress((void**)&k,   g_k);
    cudaGetSymbolAddress((void**)&v,   g_v);
    cudaGetSymbolAddress((void**)&a,   g_a);
    cudaGetSymbolAddress((void**)&x1,  g_x1);
    cudaGetSymbolAddress((void**)&y,   g_y);
    cudaGetSymbolAddress((void**)&tmp, g_tmp);
    cudaGetSymbolAddress((void**)&h,   g_h);
    cudaGetSymbolAddress((void**)&hid, g_hid);

    cudaFuncSetAttribute(attn_kernel, cudaFuncAttributeMaxDynamicSharedMemorySize,
                         ATTN_SMEM_BYTES);

    const dim3 blk(256);
    const dim3 gD(DDIM / 128, MM / 128);   // 8 x 16  (N=1024)
    const dim3 gF(FFD / 128, MM / 128);    // 32 x 16 (N=4096)
    const dim3 gAttn(SSEQ / 64, HH, BB);   // 16 x 16 x 2

    const float* hin = x;
    for (int l = 0; l < LNUM; l++) {
        const size_t wOff  = (size_t)l * HH * DDIM * DKK;   // QKV weights
        const size_t bOff  = (size_t)l * HH * DKK;          // QKV biases (1024)
        const size_t woOff = (size_t)l * DDIM * DDIM;       // Wo
        const size_t dOff  = (size_t)l * DDIM;              // per-D vectors
        const size_t w1Off = (size_t)l * DDIM * FFD;
        const size_t f1Off = (size_t)l * FFD;
        const size_t w2Off = (size_t)l * FFD * DDIM;

        // ---- masked self-attention ----
        sgemm_kernel<true, false, false><<<gD, blk>>>(hin, Wq1 + wOff, bq1 + bOff, nullptr, q, MM, DDIM, DDIM);
        sgemm_kernel<true, false, false><<<gD, blk>>>(hin, Wk1 + wOff, bk1 + bOff, nullptr, k, MM, DDIM, DDIM);
        sgemm_kernel<true, false, false><<<gD, blk>>>(hin, Wv1 + wOff, bv1 + bOff, nullptr, v, MM, DDIM, DDIM);
        attn_kernel<<<gAttn, blk, ATTN_SMEM_BYTES>>>(q, k, v, a, maskp);
        sgemm_kernel<false, false, true><<<gD, blk>>>(a, Wo1 + woOff, bo1 + dOff, hin, tmp, MM, DDIM, DDIM);
        bn_kernel<<<SSEQ, blk>>>(tmp, g1 + dOff, be1 + dOff, x1);

        // ---- second (unmasked) self-attention; residual from block input ----
        sgemm_kernel<true, false, false><<<gD, blk>>>(x1, Wq2 + wOff, bq2 + bOff, nullptr, q, MM, DDIM, DDIM);
        sgemm_kernel<true, false, false><<<gD, blk>>>(x1, Wk2 + wOff, bk2 + bOff, nullptr, k, MM, DDIM, DDIM);
        sgemm_kernel<true, false, false><<<gD, blk>>>(x1, Wv2 + wOff, bv2 + bOff, nullptr, v, MM, DDIM, DDIM);
        attn_kernel<<<gAttn, blk, ATTN_SMEM_BYTES>>>(q, k, v, a, nullptr);
        sgemm_kernel<false, false, true><<<gD, blk>>>(a, Wo2 + woOff, bo2 + dOff, hin, tmp, MM, DDIM, DDIM);
        bn_kernel<<<SSEQ, blk>>>(tmp, g2 + dOff, be2 + dOff, y);

        // ---- FFN; residual from x1 ----
        sgemm_kernel<false, true, false><<<gF, blk>>>(y, W1 + w1Off, bf1 + f1Off, nullptr, hid, MM, FFD, DDIM);
        sgemm_kernel<false, false, true><<<gD, blk>>>(hid, W2 + w2Off, bf2 + dOff, x1, tmp, MM, DDIM, FFD);

        float* dst = (l == LNUM - 1) ? (float*)d_out : h;
        bn_kernel<<<SSEQ, blk>>>(tmp, g3 + dOff, be3 + dOff, dst);
        hin = h;
    }
}

// round 3
// speedup vs baseline: 2.8834x; 2.8834x over previous
#include <cuda_runtime.h>
#include <cstdint>
#include <cstddef>

// Problem dims
#define LNUM 4
#define BB 2
#define SSEQ 1024
#define DDIM 1024
#define HH 16
#define DKK 64
#define FFD 4096
#define MM (BB * SSEQ)   // 2048 rows

// ---------------------------------------------------------------------------
// Scratch buffers (device globals — no allocations allowed)
// ---------------------------------------------------------------------------
__device__ float g_q[MM * DDIM];
__device__ float g_k[MM * DDIM];
__device__ float g_v[MM * DDIM];
__device__ float g_a[MM * DDIM];
__device__ float g_x1[MM * DDIM];
__device__ float g_y[MM * DDIM];
__device__ float g_tmp[MM * DDIM];
__device__ float g_h[MM * DDIM];
__device__ float g_hid[MM * FFD];

// ---------------------------------------------------------------------------
// cp.async helpers
// ---------------------------------------------------------------------------
__device__ __forceinline__ void cp_async16(uint32_t smem_dst, const void* gsrc) {
    asm volatile("cp.async.cg.shared.global [%0], [%1], 16;" :: "r"(smem_dst), "l"(gsrc));
}
__device__ __forceinline__ void cp_commit() {
    asm volatile("cp.async.commit_group;");
}
__device__ __forceinline__ uint32_t f2tf32(float f) {
    uint32_t u;
    asm("cvt.rna.tf32.f32 %0, %1;" : "=r"(u) : "f"(f));
    return u;
}
__device__ __forceinline__ void mma_tf32(float c[4], const uint32_t a[4], const uint32_t b[2]) {
    asm volatile(
        "mma.sync.aligned.m16n8k8.row.col.f32.tf32.tf32.f32 "
        "{%0,%1,%2,%3}, {%4,%5,%6,%7}, {%8,%9}, {%0,%1,%2,%3};"
        : "+f"(c[0]), "+f"(c[1]), "+f"(c[2]), "+f"(c[3])
        : "r"(a[0]), "r"(a[1]), "r"(a[2]), "r"(a[3]), "r"(b[0]), "r"(b[1]));
}

// ---------------------------------------------------------------------------
// TF32 tensor-core GEMM: C[M,N] = A[M,K] @ B + bias (+ residual) (+ relu)
// HEADED: B element (k,n) at ((n>>6)*K + k)*64 + (n&63)  (weights (H,D,DK))
// else:   B row-major [K,N]
// CTA tile 128x128, K-chunk 32, 256 threads = 8 warps (2x4 of 64x32 each),
// m16n8k8 tf32 atoms, 2-stage cp.async double buffering.
// M,N multiples of 128; K multiple of 32 (holds for all our shapes).
// ---------------------------------------------------------------------------
#define GEMM_SMEM_FLOATS (2 * 128 * 36 + 2 * 32 * 132)
#define GEMM_SMEM_BYTES (GEMM_SMEM_FLOATS * 4)

template <bool HEADED, bool RELU, bool RESID>
__global__ __launch_bounds__(256, 1)
void tgemm_kernel(const float* __restrict__ A, const float* __restrict__ B,
                  const float* __restrict__ bias, const float* __restrict__ R,
                  float* __restrict__ C, int M, int N, int K)
{
    extern __shared__ float smf[];
    float (*As)[128][36]  = (float(*)[128][36])smf;                  // [2][128][36]
    float (*Bs)[32][132]  = (float(*)[32][132])(smf + 2 * 128 * 36); // [2][32][132]

    const int tid  = threadIdx.x;
    const int lane = tid & 31;
    const int warp = tid >> 5;
    const int warpM = (warp & 1) * 64;   // 2 warp-rows
    const int warpN = (warp >> 1) * 32;  // 4 warp-cols
    const int row_blk = blockIdx.y * 128;
    const int col_blk = blockIdx.x * 128;

    // loader mapping
    const int a_r = tid >> 3;          // 0..31
    const int a_c = (tid & 7) * 4;     // 0,4,..28
    const int b_k = tid >> 5;          // 0..7
    const int b_n = (tid & 31) * 4;    // 0..124

    const int lg = lane >> 2;          // groupID 0..7
    const int lt = lane & 3;           // thread-in-group 0..3

    float acc[4][4][4];
#pragma unroll
    for (int i = 0; i < 4; i++)
#pragma unroll
        for (int j = 0; j < 4; j++)
#pragma unroll
            for (int r = 0; r < 4; r++) acc[i][j][r] = 0.f;

    const int nk = K >> 5;

    auto prefetch = [&](int kc, int buf) {
        const float* Ag = A + (size_t)row_blk * K + kc * 32;
#pragma unroll
        for (int i = 0; i < 4; i++) {
            int r = a_r + i * 32;
            uint32_t dst = (uint32_t)__cvta_generic_to_shared(&As[buf][r][a_c]);
            cp_async16(dst, Ag + (size_t)r * K + a_c);
        }
#pragma unroll
        for (int i = 0; i < 4; i++) {
            int k = b_k + i * 8;
            uint32_t dst = (uint32_t)__cvta_generic_to_shared(&Bs[buf][k][b_n]);
            const float* src;
            if (HEADED) {
                int n = col_blk + b_n;
                src = B + ((size_t)(n >> 6) * K + kc * 32 + k) * 64 + (n & 63);
            } else {
                src = B + (size_t)(kc * 32 + k) * N + col_blk + b_n;
            }
            cp_async16(dst, src);
        }
    };

    prefetch(0, 0);
    cp_commit();

    for (int kc = 0; kc < nk; kc++) {
        if (kc + 1 < nk) {
            prefetch(kc + 1, (kc + 1) & 1);
            cp_commit();
            asm volatile("cp.async.wait_group 1;");
        } else {
            asm volatile("cp.async.wait_group 0;");
        }
        __syncthreads();

        const int buf = kc & 1;
#pragma unroll
        for (int ks = 0; ks < 4; ks++) {
            const int k0 = ks * 8;
            uint32_t afr[4][4];
#pragma unroll
            for (int i = 0; i < 4; i++) {
                int m = warpM + i * 16 + lg;
                afr[i][0] = f2tf32(As[buf][m][k0 + lt]);
                afr[i][1] = f2tf32(As[buf][m + 8][k0 + lt]);
                afr[i][2] = f2tf32(As[buf][m][k0 + lt + 4]);
                afr[i][3] = f2tf32(As[buf][m + 8][k0 + lt + 4]);
            }
            uint32_t bfr[4][2];
#pragma unroll
            for (int j = 0; j < 4; j++) {
                int n = warpN + j * 8 + lg;
                bfr[j][0] = f2tf32(Bs[buf][k0 + lt][n]);
                bfr[j][1] = f2tf32(Bs[buf][k0 + lt + 4][n]);
            }
#pragma unroll
            for (int i = 0; i < 4; i++)
#pragma unroll
                for (int j = 0; j < 4; j++)
                    mma_tf32(acc[i][j], afr[i], bfr[j]);
        }
        __syncthreads();
    }

    // Epilogue: c0,c1 at (row, 2*lt), (row, 2*lt+1); c2,c3 at row+8.
#pragma unroll
    for (int i = 0; i < 4; i++) {
#pragma unroll
        for (int j = 0; j < 4; j++) {
            int r0 = row_blk + warpM + i * 16 + lg;
            int c0 = col_blk + warpN + j * 8 + 2 * lt;
            float bv0 = bias[c0], bv1 = bias[c0 + 1];
            float v0 = acc[i][j][0] + bv0;
            float v1 = acc[i][j][1] + bv1;
            float v2 = acc[i][j][2] + bv0;
            float v3 = acc[i][j][3] + bv1;
            if (RESID) {
                const float2 r0v = *(const float2*)&R[(size_t)r0 * N + c0];
                const float2 r1v = *(const float2*)&R[(size_t)(r0 + 8) * N + c0];
                v0 += r0v.x; v1 += r0v.y; v2 += r1v.x; v3 += r1v.y;
            }
            if (RELU) {
                v0 = fmaxf(v0, 0.f); v1 = fmaxf(v1, 0.f);
                v2 = fmaxf(v2, 0.f); v3 = fmaxf(v3, 0.f);
            }
            *(float2*)&C[(size_t)r0 * N + c0]       = make_float2(v0, v1);
            *(float2*)&C[(size_t)(r0 + 8) * N + c0] = make_float2(v2, v3);
        }
    }
}

// ---------------------------------------------------------------------------
// Flash attention: q,k,v in (B, S, H*DK) concat layout; out in same layout.
// One CTA per (b, h, 64-row q tile). Online softmax over kv tiles of 64.
// kv length = *maskp (attn1) or S (maskp == nullptr).
// ---------------------------------------------------------------------------
#define AP 65   // pitch for transposed 64x64 tiles
#define VP 68   // pitch for row-major V tile (float4-aligned)
#define ATTN_SMEM_FLOATS (3 * 64 * AP + 64 * VP + 3 * 64)
#define ATTN_SMEM_BYTES (ATTN_SMEM_FLOATS * 4)

__global__ __launch_bounds__(256)
void attn_kernel(const float* __restrict__ q, const float* __restrict__ k,
                 const float* __restrict__ v, float* __restrict__ out,
                 const int* __restrict__ maskp)
{
    extern __shared__ float sm[];
    float* Qs  = sm;                  // [64][AP] transposed: Qs[d*AP + r]
    float* Ks  = Qs + 64 * AP;        // [64][AP] transposed: Ks[d*AP + c]
    float* Ps  = Ks + 64 * AP;        // [64][AP] row-major scores/probs
    float* Vs  = Ps + 64 * AP;        // [64][VP] row-major: Vs[c*VP + d]
    float* mrow = Vs + 64 * VP;       // [64]
    float* lrow = mrow + 64;          // [64]
    float* srow = lrow + 64;          // [64]

    const int tid = threadIdx.x;
    const int tx = tid & 15;          // col group
    const int ty = tid >> 4;          // row group
    const int qt = blockIdx.x;
    const int h  = blockIdx.y;
    const int b  = blockIdx.z;

    int kvlen = maskp ? *maskp : SSEQ;
    if (kvlen > SSEQ) kvlen = SSEQ;
    if (kvlen < 1) kvlen = 1;

    const float* qb = q + ((size_t)(b * SSEQ) + qt * 64) * DDIM + h * DKK;
    const float* kb = k + (size_t)(b * SSEQ) * DDIM + h * DKK;
    const float* vb = v + (size_t)(b * SSEQ) * DDIM + h * DKK;

    // load Q tile (transposed)
#pragma unroll
    for (int c = 0; c < 4; c++) {
        int idx = tid + c * 256;
        int r = idx >> 4;
        int d0 = (idx & 15) * 4;
        float4 t = *(const float4*)&qb[(size_t)r * DDIM + d0];
        Qs[(d0 + 0) * AP + r] = t.x;
        Qs[(d0 + 1) * AP + r] = t.y;
        Qs[(d0 + 2) * AP + r] = t.z;
        Qs[(d0 + 3) * AP + r] = t.w;
    }
    if (tid < 64) { mrow[tid] = -1e30f; lrow[tid] = 0.f; }

    float O[4][4];
#pragma unroll
    for (int i = 0; i < 4; i++)
#pragma unroll
        for (int j = 0; j < 4; j++) O[i][j] = 0.f;

    const int nt = (kvlen + 63) >> 6;
    for (int t = 0; t < nt; t++) {
        __syncthreads();   // previous-iteration consumers of Ks/Vs done
        const float* kt = kb + (size_t)(t * 64) * DDIM;
        const float* vt = vb + (size_t)(t * 64) * DDIM;
#pragma unroll
        for (int c = 0; c < 4; c++) {
            int idx = tid + c * 256;
            int r = idx >> 4;
            int d0 = (idx & 15) * 4;
            float4 tk = *(const float4*)&kt[(size_t)r * DDIM + d0];
            Ks[(d0 + 0) * AP + r] = tk.x;
            Ks[(d0 + 1) * AP + r] = tk.y;
            Ks[(d0 + 2) * AP + r] = tk.z;
            Ks[(d0 + 3) * AP + r] = tk.w;
            float4 tv = *(const float4*)&vt[(size_t)r * DDIM + d0];
            *(float4*)&Vs[r * VP + d0] = tv;
        }
        __syncthreads();

        // scores: s = (Q K^T) * 1/sqrt(64)
        float sacc[4][4];
#pragma unroll
        for (int i = 0; i < 4; i++)
#pragma unroll
            for (int j = 0; j < 4; j++) sacc[i][j] = 0.f;
#pragma unroll 8
        for (int d = 0; d < 64; d++) {
            float aq[4], bk[4];
#pragma unroll
            for (int i = 0; i < 4; i++) aq[i] = Qs[d * AP + ty * 4 + i];
#pragma unroll
            for (int j = 0; j < 4; j++) bk[j] = Ks[d * AP + tx * 4 + j];
#pragma unroll
            for (int i = 0; i < 4; i++)
#pragma unroll
                for (int j = 0; j < 4; j++) sacc[i][j] += aq[i] * bk[j];
        }
        const int cbase = t * 64 + tx * 4;
#pragma unroll
        for (int i = 0; i < 4; i++)
#pragma unroll
            for (int j = 0; j < 4; j++) {
                float val = (cbase + j < kvlen) ? sacc[i][j] * 0.125f : -1e30f;
                Ps[(ty * 4 + i) * AP + tx * 4 + j] = val;
            }
        __syncthreads();

        // per-row online softmax (one thread per row)
        if (tid < 64) {
            float mo = mrow[tid];
            float mt = -1e30f;
            float* pr = &Ps[tid * AP];
#pragma unroll 8
            for (int c = 0; c < 64; c++) mt = fmaxf(mt, pr[c]);
            float mn = fmaxf(mo, mt);
            float sc = __expf(mo - mn);
            float sum = 0.f;
#pragma unroll 8
            for (int c = 0; c < 64; c++) {
                float p = __expf(pr[c] - mn);
                pr[c] = p;
                sum += p;
            }
            lrow[tid] = lrow[tid] * sc + sum;
            mrow[tid] = mn;
            srow[tid] = sc;
        }
        __syncthreads();

        // rescale O, accumulate O += P @ V
        float sci[4];
#pragma unroll
        for (int i = 0; i < 4; i++) sci[i] = srow[ty * 4 + i];
#pragma unroll
        for (int i = 0; i < 4; i++)
#pragma unroll
            for (int j = 0; j < 4; j++) O[i][j] *= sci[i];
#pragma unroll 8
        for (int c = 0; c < 64; c++) {
            float pv[4];
#pragma unroll
            for (int i = 0; i < 4; i++) pv[i] = Ps[(ty * 4 + i) * AP + c];
            float4 vv = *(const float4*)&Vs[c * VP + tx * 4];
#pragma unroll
            for (int i = 0; i < 4; i++) {
                O[i][0] += pv[i] * vv.x;
                O[i][1] += pv[i] * vv.y;
                O[i][2] += pv[i] * vv.z;
                O[i][3] += pv[i] * vv.w;
            }
        }
    }
    __syncthreads();

    float* ob = out + ((size_t)(b * SSEQ) + qt * 64) * DDIM + h * DKK;
#pragma unroll
    for (int i = 0; i < 4; i++) {
        float inv = 1.f / lrow[ty * 4 + i];
#pragma unroll
        for (int j = 0; j < 4; j++)
            ob[(size_t)(ty * 4 + i) * DDIM + tx * 4 + j] = O[i][j] * inv;
    }
}

// ---------------------------------------------------------------------------
// BatchNorm over axes (B, D) per s index (channel axis = 1, S==D==1024).
// ---------------------------------------------------------------------------
__global__ __launch_bounds__(256)
void bn_kernel(const float* __restrict__ in, const float* __restrict__ g,
               const float* __restrict__ be, float* __restrict__ out)
{
    __shared__ float s_sum[256];
    __shared__ float s_sq[256];
    __shared__ float s_mean, s_rs;

    const int s = blockIdx.x;
    const int tid = threadIdx.x;

    float sum = 0.f, sq = 0.f;
#pragma unroll
    for (int b = 0; b < BB; b++) {
        const float* row = in + ((size_t)b * SSEQ + s) * DDIM;
        for (int d = tid; d < DDIM; d += 256) {
            float x = row[d];
            sum += x;
            sq += x * x;
        }
    }
    s_sum[tid] = sum;
    s_sq[tid] = sq;
    __syncthreads();
    for (int o = 128; o > 0; o >>= 1) {
        if (tid < o) { s_sum[tid] += s_sum[tid + o]; s_sq[tid] += s_sq[tid + o]; }
        __syncthreads();
    }
    if (tid == 0) {
        const float inv_n = 1.f / (BB * DDIM);
        float mean = s_sum[0] * inv_n;
        float var = s_sq[0] * inv_n - mean * mean;
        s_mean = mean;
        s_rs = rsqrtf(var + 1e-5f);
    }
    __syncthreads();
    const float gg = g[s], bb2 = be[s], mean = s_mean, rs = s_rs;
#pragma unroll
    for (int b = 0; b < BB; b++) {
        const float* row = in + ((size_t)b * SSEQ + s) * DDIM;
        float* orow = out + ((size_t)b * SSEQ + s) * DDIM;
        for (int d = tid; d < DDIM; d += 256) {
            orow[d] = (row[d] - mean) * rs * gg + bb2;
        }
    }
}

// ---------------------------------------------------------------------------
// Host orchestration
// ---------------------------------------------------------------------------
extern "C" void kernel_launch(void* const* d_in, const int* in_sizes, int n_in,
                              void* d_out, int out_size)
{
    const float* x   = (const float*)d_in[0];
    const float* Wq1 = (const float*)d_in[1];
    const float* bq1 = (const float*)d_in[2];
    const float* Wk1 = (const float*)d_in[3];
    const float* bk1 = (const float*)d_in[4];
    const float* Wv1 = (const float*)d_in[5];
    const float* bv1 = (const float*)d_in[6];
    const float* Wo1 = (const float*)d_in[7];
    const float* bo1 = (const float*)d_in[8];
    const float* Wq2 = (const float*)d_in[9];
    const float* bq2 = (const float*)d_in[10];
    const float* Wk2 = (const float*)d_in[11];
    const float* bk2 = (const float*)d_in[12];
    const float* Wv2 = (const float*)d_in[13];
    const float* bv2 = (const float*)d_in[14];
    const float* Wo2 = (const float*)d_in[15];
    const float* bo2 = (const float*)d_in[16];
    const float* g1  = (const float*)d_in[17];
    const float* be1 = (const float*)d_in[18];
    const float* g2  = (const float*)d_in[19];
    const float* be2 = (const float*)d_in[20];
    const float* g3  = (const float*)d_in[21];
    const float* be3 = (const float*)d_in[22];
    const float* W1  = (const float*)d_in[23];
    const float* bf1 = (const float*)d_in[24];
    const float* W2  = (const float*)d_in[25];
    const float* bf2 = (const float*)d_in[26];
    const int*   maskp = (const int*)d_in[27];

    float *q, *k, *v, *a, *x1, *y, *tmp, *h, *hid;
    cudaGetSymbolAddress((void**)&q,   g_q);
    cudaGetSymbolAddress((void**)&k,   g_k);
    cudaGetSymbolAddress((void**)&v,   g_v);
    cudaGetSymbolAddress((void**)&a,   g_a);
    cudaGetSymbolAddress((void**)&x1,  g_x1);
    cudaGetSymbolAddress((void**)&y,   g_y);
    cudaGetSymbolAddress((void**)&tmp, g_tmp);
    cudaGetSymbolAddress((void**)&h,   g_h);
    cudaGetSymbolAddress((void**)&hid, g_hid);

    cudaFuncSetAttribute(attn_kernel, cudaFuncAttributeMaxDynamicSharedMemorySize,
                         ATTN_SMEM_BYTES);
    cudaFuncSetAttribute(tgemm_kernel<true, false, false>,
                         cudaFuncAttributeMaxDynamicSharedMemorySize, GEMM_SMEM_BYTES);
    cudaFuncSetAttribute(tgemm_kernel<false, false, true>,
                         cudaFuncAttributeMaxDynamicSharedMemorySize, GEMM_SMEM_BYTES);
    cudaFuncSetAttribute(tgemm_kernel<false, true, false>,
                         cudaFuncAttributeMaxDynamicSharedMemorySize, GEMM_SMEM_BYTES);

    const dim3 blk(256);
    const dim3 gD(DDIM / 128, MM / 128);   // 8 x 16  (N=1024)
    const dim3 gF(FFD / 128, MM / 128);    // 32 x 16 (N=4096)
    const dim3 gAttn(SSEQ / 64, HH, BB);   // 16 x 16 x 2

    const float* hin = x;
    for (int l = 0; l < LNUM; l++) {
        const size_t wOff  = (size_t)l * HH * DDIM * DKK;   // QKV weights
        const size_t bOff  = (size_t)l * HH * DKK;          // QKV biases (1024)
        const size_t woOff = (size_t)l * DDIM * DDIM;       // Wo
        const size_t dOff  = (size_t)l * DDIM;              // per-D vectors
        const size_t w1Off = (size_t)l * DDIM * FFD;
        const size_t f1Off = (size_t)l * FFD;
        const size_t w2Off = (size_t)l * FFD * DDIM;

        // ---- masked self-attention ----
        tgemm_kernel<true, false, false><<<gD, blk, GEMM_SMEM_BYTES>>>(hin, Wq1 + wOff, bq1 + bOff, nullptr, q, MM, DDIM, DDIM);
        tgemm_kernel<true, false, false><<<gD, blk, GEMM_SMEM_BYTES>>>(hin, Wk1 + wOff, bk1 + bOff, nullptr, k, MM, DDIM, DDIM);
        tgemm_kernel<true, false, false><<<gD, blk, GEMM_SMEM_BYTES>>>(hin, Wv1 + wOff, bv1 + bOff, nullptr, v, MM, DDIM, DDIM);
        attn_kernel<<<gAttn, blk, ATTN_SMEM_BYTES>>>(q, k, v, a, maskp);
        tgemm_kernel<false, false, true><<<gD, blk, GEMM_SMEM_BYTES>>>(a, Wo1 + woOff, bo1 + dOff, hin, tmp, MM, DDIM, DDIM);
        bn_kernel<<<SSEQ, blk>>>(tmp, g1 + dOff, be1 + dOff, x1);

        // ---- second (unmasked) self-attention; residual from block input ----
        tgemm_kernel<true, false, false><<<gD, blk, GEMM_SMEM_BYTES>>>(x1, Wq2 + wOff, bq2 + bOff, nullptr, q, MM, DDIM, DDIM);
        tgemm_kernel<true, false, false><<<gD, blk, GEMM_SMEM_BYTES>>>(x1, Wk2 + wOff, bk2 + bOff, nullptr, k, MM, DDIM, DDIM);
        tgemm_kernel<true, false, false><<<gD, blk, GEMM_SMEM_BYTES>>>(x1, Wv2 + wOff, bv2 + bOff, nullptr, v, MM, DDIM, DDIM);
        attn_kernel<<<gAttn, blk, ATTN_SMEM_BYTES>>>(q, k, v, a, nullptr);
        tgemm_kernel<false, false, true><<<gD, blk, GEMM_SMEM_BYTES>>>(a, Wo2 + woOff, bo2 + dOff, hin, tmp, MM, DDIM, DDIM);
        bn_kernel<<<SSEQ, blk>>>(tmp, g2 + dOff, be2 + dOff, y);

        // ---- FFN; residual from x1 ----
        tgemm_kernel<false, true, false><<<gF, blk, GEMM_SMEM_BYTES>>>(y, W1 + w1Off, bf1 + f1Off, nullptr, hid, MM, FFD, DDIM);
        tgemm_kernel<false, false, true><<<gD, blk, GEMM_SMEM_BYTES>>>(hid, W2 + w2Off, bf2 + dOff, x1, tmp, MM, DDIM, FFD);

        float* dst = (l == LNUM - 1) ? (float*)d_out : h;
        bn_kernel<<<SSEQ, blk>>>(tmp, g3 + dOff, be3 + dOff, dst);
        hin = h;
    }
}